// round 1
// baseline (speedup 1.0000x reference)
#include <cuda_runtime.h>
#include <math.h>

#define BS    64
#define FDIM  256
#define MDIM  128
#define KC    16
#define NTILE (FDIM / KC)          // 16
#define NPAIRS (BS * (BS + 1) / 2) // 2080
#define BINS  8

typedef unsigned long long ull;

__device__ __forceinline__ ull pack2(float lo, float hi) {
    ull r;
    asm("mov.b64 %0, {%1, %2};" : "=l"(r) : "f"(lo), "f"(hi));
    return r;
}
__device__ __forceinline__ void unpack2(ull v, float& lo, float& hi) {
    asm("mov.b64 {%0, %1}, %2;" : "=f"(lo), "=f"(hi) : "l"(v));
}
__device__ __forceinline__ ull ffma2(ull a, ull b, ull c) {
    ull d;
    asm("fma.rn.f32x2 %0, %1, %2, %3;" : "=l"(d) : "l"(a), "l"(b), "l"(c));
    return d;
}

__global__ __launch_bounds__(256, 2)
void pairhist_kernel(const float* __restrict__ matf1,
                     const float* __restrict__ matf2,
                     float* __restrict__ out) {
    const int p    = blockIdx.x;   // triangular pair index, a <= b
    const int midx = blockIdx.y;   // 0 -> matf1, 1 -> matf2

    // decode p -> (a, bq) with p = bq*(bq+1)/2 + a, a in [0, bq]
    int bq = (int)floorf((sqrtf(8.0f * (float)p + 1.0f) - 1.0f) * 0.5f);
    while ((bq + 1) * (bq + 2) / 2 <= p) ++bq;
    while (bq * (bq + 1) / 2 > p) --bq;
    const int a = p - bq * (bq + 1) / 2;

    const float* base = midx ? matf2 : matf1;
    const float* Aptr = base + (size_t)a  * FDIM * MDIM;  // [F, M], K-major
    const float* Bptr = base + (size_t)bq * FDIM * MDIM;

    __shared__ __align__(16) float As[2][KC][MDIM];
    __shared__ __align__(16) float Bsm[2][KC][MDIM];
    __shared__ float redmn[8], redmx[8];
    __shared__ ull   redh[8][2];

    const int tid = threadIdx.x;
    const int tx  = tid & 15;     // n-block: cols tx*8 .. tx*8+7
    const int ty  = tid >> 4;     // m-block: rows ty*8 .. ty*8+7

    ull acc[8][4];
    #pragma unroll
    for (int i = 0; i < 8; i++)
        #pragma unroll
        for (int j = 0; j < 4; j++) acc[i][j] = 0ull;

    const float4* Ag = reinterpret_cast<const float4*>(Aptr);
    const float4* Bg = reinterpret_cast<const float4*>(Bptr);

    // preload tile 0
    float4 pa0 = Ag[tid], pa1 = Ag[tid + 256];
    float4 pb0 = Bg[tid], pb1 = Bg[tid + 256];
    ((float4*)As[0])[tid]        = pa0;
    ((float4*)As[0])[tid + 256]  = pa1;
    ((float4*)Bsm[0])[tid]       = pb0;
    ((float4*)Bsm[0])[tid + 256] = pb1;
    __syncthreads();

    int cur = 0;
    for (int t = 0; t < NTILE; t++) {
        if (t + 1 < NTILE) {
            const int gbase = (t + 1) * (KC * MDIM / 4);   // 512 float4 per tile
            pa0 = Ag[gbase + tid]; pa1 = Ag[gbase + tid + 256];
            pb0 = Bg[gbase + tid]; pb1 = Bg[gbase + tid + 256];
        }
        #pragma unroll
        for (int k = 0; k < KC; k++) {
            const float4 a0 = *(const float4*)&As[cur][k][ty * 8];
            const float4 a1 = *(const float4*)&As[cur][k][ty * 8 + 4];
            ull ap[8];
            ap[0] = pack2(a0.x, a0.x); ap[1] = pack2(a0.y, a0.y);
            ap[2] = pack2(a0.z, a0.z); ap[3] = pack2(a0.w, a0.w);
            ap[4] = pack2(a1.x, a1.x); ap[5] = pack2(a1.y, a1.y);
            ap[6] = pack2(a1.z, a1.z); ap[7] = pack2(a1.w, a1.w);
            const ulonglong2* bp = (const ulonglong2*)&Bsm[cur][k][tx * 8];
            const ulonglong2 b01 = bp[0];
            const ulonglong2 b23 = bp[1];
            #pragma unroll
            for (int i = 0; i < 8; i++) {
                acc[i][0] = ffma2(ap[i], b01.x, acc[i][0]);
                acc[i][1] = ffma2(ap[i], b01.y, acc[i][1]);
                acc[i][2] = ffma2(ap[i], b23.x, acc[i][2]);
                acc[i][3] = ffma2(ap[i], b23.y, acc[i][3]);
            }
        }
        if (t + 1 < NTILE) {
            const int nxt = cur ^ 1;
            ((float4*)As[nxt])[tid]        = pa0;
            ((float4*)As[nxt])[tid + 256]  = pa1;
            ((float4*)Bsm[nxt])[tid]       = pb0;
            ((float4*)Bsm[nxt])[tid + 256] = pb1;
        }
        __syncthreads();
        cur ^= 1;
    }

    // ---- epilogue: unpack 64 values ----
    float v[64];
    #pragma unroll
    for (int i = 0; i < 8; i++)
        #pragma unroll
        for (int j = 0; j < 4; j++)
            unpack2(acc[i][j], v[(i * 4 + j) * 2], v[(i * 4 + j) * 2 + 1]);

    // local min/max
    float mn = v[0], mx = v[0];
    #pragma unroll
    for (int q = 1; q < 64; q++) { mn = fminf(mn, v[q]); mx = fmaxf(mx, v[q]); }

    // warp reduce min/max
    #pragma unroll
    for (int o = 16; o > 0; o >>= 1) {
        mn = fminf(mn, __shfl_xor_sync(0xffffffffu, mn, o));
        mx = fmaxf(mx, __shfl_xor_sync(0xffffffffu, mx, o));
    }
    const int wid  = tid >> 5;
    const int lane = tid & 31;
    if (lane == 0) { redmn[wid] = mn; redmx[wid] = mx; }
    __syncthreads();
    mn = redmn[0]; mx = redmx[0];
    #pragma unroll
    for (int w = 1; w < 8; w++) { mn = fminf(mn, redmn[w]); mx = fmaxf(mx, redmx[w]); }

    const float denom = (mx > mn) ? (mx - mn) : 1.0f;

    // branch-free histogram: 8 bins packed as 16-bit fields in two u64
    ull h0 = 0ull, h1 = 0ull;
    #pragma unroll
    for (int q = 0; q < 64; q++) {
        const float tt = (v[q] - mn) / denom * 8.0f;   // matches reference op order
        int bi = (int)tt;                              // tt >= 0
        if (bi > 7) bi = 7;
        const ull one = 1ull << ((bi & 3) << 4);
        if (bi < 4) h0 += one; else h1 += one;
    }
    #pragma unroll
    for (int o = 16; o > 0; o >>= 1) {
        h0 += __shfl_xor_sync(0xffffffffu, h0, o);
        h1 += __shfl_xor_sync(0xffffffffu, h1, o);
    }
    if (lane == 0) { redh[wid][0] = h0; redh[wid][1] = h1; }
    __syncthreads();

    if (tid == 0) {
        ull H0 = 0ull, H1 = 0ull;
        #pragma unroll
        for (int w = 0; w < 8; w++) { H0 += redh[w][0]; H1 += redh[w][1]; }
        float c[8];
        #pragma unroll
        for (int bn = 0; bn < 4; bn++) {
            c[bn]     = (float)((H0 >> (bn * 16)) & 0xFFFFull);
            c[bn + 4] = (float)((H1 >> (bn * 16)) & 0xFFFFull);
        }
        float ss = 0.0f;
        #pragma unroll
        for (int bn = 0; bn < 8; bn++) ss += c[bn] * c[bn];
        float nrm = sqrtf(ss);
        nrm = fmaxf(nrm, 1e-12f);

        const int row1 = a * BS + bq;
        const int row2 = bq * BS + a;
        float* o1 = out + row1 * 16 + midx * 8;
        float* o2 = out + row2 * 16 + midx * 8;
        #pragma unroll
        for (int bn = 0; bn < 8; bn++) {
            const float val = c[bn] / nrm;
            o1[bn] = val;
            o2[bn] = val;   // symmetry: hist(a,b) == hist(b,a)
        }
    }
}

extern "C" void kernel_launch(void* const* d_in, const int* in_sizes, int n_in,
                              void* d_out, int out_size) {
    const float* matf1 = (const float*)d_in[0];
    const float* matf2 = (const float*)d_in[1];
    float* out = (float*)d_out;
    dim3 grid(NPAIRS, 2);
    pairhist_kernel<<<grid, 256>>>(matf1, matf2, out);
}

// round 4
// speedup vs baseline: 1.9614x; 1.9614x over previous
#include <cuda_runtime.h>
#include <cuda_fp16.h>
#include <cstdint>
#include <math.h>

#define BSZ    64
#define FDIM   256
#define MDIM   128
#define NPAIRS 2080            // 64*65/2 triangular pairs
#define KC     32              // K per chunk
#define NCH    (FDIM / KC)     // 8
#define TILE_B 8192            // 128 rows x 64B (32 fp16)
#define STAGE_B (4 * TILE_B)   // Ah, Al, Bh, Bl = 32KB
typedef unsigned long long ull;

// fp16 split scratch: [tensor][hi/lo][b][m][f], f contiguous = 16 MB
__device__ __align__(16) __half XS[2][2][BSZ][MDIM][FDIM];

// ---------------- pre-pass: transpose + fp16 hi/lo split ----------------
__global__ void split_transpose(const float* __restrict__ m1,
                                const float* __restrict__ m2) {
    __shared__ float tile[32][33];
    const int b  = blockIdx.x;
    const int f0 = blockIdx.y * 32;
    const int mt = blockIdx.z & 3, t = blockIdx.z >> 2;
    const int m0 = mt * 32;
    const float* src = t ? m2 : m1;
    const int tx = threadIdx.x, ty = threadIdx.y;
    #pragma unroll
    for (int i = 0; i < 4; i++) {
        int f = f0 + ty + i * 8;
        tile[ty + i * 8][tx] = src[((size_t)b * FDIM + f) * MDIM + m0 + tx];
    }
    __syncthreads();
    #pragma unroll
    for (int i = 0; i < 4; i++) {
        int m = m0 + ty + i * 8;
        int f = f0 + tx;
        float v = tile[tx][ty + i * 8];
        __half hi = __float2half_rn(v);
        __half lo = __float2half_rn(v - __half2float(hi));
        XS[t][0][b][m][f] = hi;
        XS[t][1][b][m][f] = lo;
    }
}

// ---------------- helpers ----------------
__device__ __forceinline__ uint32_t s2u(const void* p) {
    uint32_t a;
    asm("{ .reg .u64 t; cvta.to.shared.u64 t, %1; cvt.u32.u64 %0, t; }"
        : "=r"(a) : "l"(p));
    return a;
}
__device__ __forceinline__ void cpasync16(uint32_t dst, const void* src) {
    asm volatile("cp.async.cg.shared.global [%0], [%1], 16;"
                 :: "r"(dst), "l"(src));
}
template <int N>
__device__ __forceinline__ void cp_wait() {
    asm volatile("cp.async.wait_group %0;" :: "n"(N) : "memory");
}
__device__ __forceinline__ void ldsm4(uint32_t* r, uint32_t addr) {
    asm volatile("ldmatrix.sync.aligned.m8n8.x4.shared.b16 {%0,%1,%2,%3}, [%4];"
                 : "=r"(r[0]), "=r"(r[1]), "=r"(r[2]), "=r"(r[3]) : "r"(addr));
}
__device__ __forceinline__ void mma16816(float* c, const uint32_t* a,
                                         const uint32_t* b) {
    asm volatile(
        "mma.sync.aligned.m16n8k16.row.col.f32.f16.f16.f32 "
        "{%0,%1,%2,%3}, {%4,%5,%6,%7}, {%8,%9}, {%0,%1,%2,%3};"
        : "+f"(c[0]), "+f"(c[1]), "+f"(c[2]), "+f"(c[3])
        : "r"(a[0]), "r"(a[1]), "r"(a[2]), "r"(a[3]), "r"(b[0]), "r"(b[1]));
}
// swizzled byte offset of (row r, 16B-chunk j) inside a [128][64B] tile
__device__ __forceinline__ uint32_t swz(int r, int j) {
    return (uint32_t)(r * 64 + ((j ^ ((r >> 1) & 3)) << 4));
}

// ---------------- main kernel ----------------
__global__ __launch_bounds__(512, 1)
void pair_hmma(float* __restrict__ out) {
    extern __shared__ char dsm[];
    __shared__ float s_mn[16], s_mx[16];
    __shared__ ull   s_h[16][2];

    const int tid  = threadIdx.x;
    const int lane = tid & 31;
    const int wid  = tid >> 5;          // 0..15
    const int t    = blockIdx.y;

    // decode triangular pair p -> (a, b), a <= b
    int p = blockIdx.x;
    int b = (int)floorf((sqrtf(8.0f * (float)p + 1.0f) - 1.0f) * 0.5f);
    while ((b + 1) * (b + 2) / 2 <= p) ++b;
    while (b * (b + 1) / 2 > p) --b;
    const int a = p - b * (b + 1) / 2;

    const uint32_t sbase = s2u(dsm);
    const int m_base = (wid >> 2) * 32;
    const int n_base = (wid & 3) * 32;

    float acc[2][4][4];
    #pragma unroll
    for (int i = 0; i < 2; i++)
        #pragma unroll
        for (int j = 0; j < 4; j++)
            #pragma unroll
            for (int k = 0; k < 4; k++) acc[i][j][k] = 0.0f;

    // prefetch chunk ch into stage (4 tiles: Ah, Al, Bh, Bl)
    auto prefetch = [&](int ch) {
        const uint32_t stg = sbase + (uint32_t)(ch & 1) * STAGE_B;
        #pragma unroll
        for (int i = 0; i < 4; i++) {
            int g    = i * 512 + tid;
            int tile = g >> 9;          // 0..3
            int rem  = g & 511;
            int r    = rem >> 2;        // 0..127
            int j    = rem & 3;         // 0..3
            int hl   = tile & 1;
            int row  = (tile >> 1) ? b : a;
            const __half* src = &XS[t][hl][row][r][ch * KC + j * 8];
            cpasync16(stg + (uint32_t)tile * TILE_B + swz(r, j), src);
        }
        asm volatile("cp.async.commit_group;" ::: "memory");
    };

    prefetch(0);

    for (int ch = 0; ch < NCH; ch++) {
        if (ch < NCH - 1) prefetch(ch + 1);
        if (ch < NCH - 1) cp_wait<1>(); else cp_wait<0>();
        __syncthreads();

        const uint32_t aH = sbase + (uint32_t)(ch & 1) * STAGE_B;
        const uint32_t aL = aH + TILE_B;
        const uint32_t bH = aH + 2 * TILE_B;
        const uint32_t bL = aH + 3 * TILE_B;

        #pragma unroll
        for (int ks = 0; ks < 2; ks++) {
            uint32_t ah[2][4], al[2][4], bh[8], bl[8];
            #pragma unroll
            for (int mt = 0; mt < 2; mt++) {
                const int r = m_base + mt * 16 + (lane & 15);
                const int j = ks * 2 + (lane >> 4);
                const uint32_t off = swz(r, j);
                ldsm4(ah[mt], aH + off);
                ldsm4(al[mt], aL + off);
            }
            #pragma unroll
            for (int t2 = 0; t2 < 2; t2++) {
                const int r = n_base + t2 * 16 + ((lane >> 4) << 3) + (lane & 7);
                const int j = ks * 2 + ((lane >> 3) & 1);
                const uint32_t off = swz(r, j);
                ldsm4(&bh[4 * t2], bH + off);
                ldsm4(&bl[4 * t2], bL + off);
            }
            #pragma unroll
            for (int mt = 0; mt < 2; mt++)
                #pragma unroll
                for (int nt = 0; nt < 4; nt++) {
                    const uint32_t* bhf = &bh[(nt >> 1) * 4 + (nt & 1) * 2];
                    const uint32_t* blf = &bl[(nt >> 1) * 4 + (nt & 1) * 2];
                    mma16816(acc[mt][nt], ah[mt], bhf);
                    mma16816(acc[mt][nt], ah[mt], blf);
                    mma16816(acc[mt][nt], al[mt], bhf);
                }
        }
        __syncthreads();
    }

    // -------- epilogue: min/max + histogram over all 16384 CTA values --------
    const float* va = &acc[0][0][0];
    float mn = va[0], mx = va[0];
    #pragma unroll
    for (int q = 1; q < 32; q++) { mn = fminf(mn, va[q]); mx = fmaxf(mx, va[q]); }
    #pragma unroll
    for (int o = 16; o > 0; o >>= 1) {
        mn = fminf(mn, __shfl_xor_sync(0xffffffffu, mn, o));
        mx = fmaxf(mx, __shfl_xor_sync(0xffffffffu, mx, o));
    }
    if (lane == 0) { s_mn[wid] = mn; s_mx[wid] = mx; }
    __syncthreads();
    mn = s_mn[0]; mx = s_mx[0];
    #pragma unroll
    for (int w = 1; w < 16; w++) {
        mn = fminf(mn, s_mn[w]); mx = fmaxf(mx, s_mx[w]);
    }
    const float denom = (mx > mn) ? (mx - mn) : 1.0f;

    ull h0 = 0ull, h1 = 0ull;
    #pragma unroll
    for (int q = 0; q < 32; q++) {
        const float tt = (va[q] - mn) / denom * 8.0f;
        int bi = (int)tt;
        if (bi > 7) bi = 7;
        const ull one = 1ull << ((bi & 3) << 4);
        if (bi < 4) h0 += one; else h1 += one;
    }
    #pragma unroll
    for (int o = 16; o > 0; o >>= 1) {
        h0 += __shfl_xor_sync(0xffffffffu, h0, o);
        h1 += __shfl_xor_sync(0xffffffffu, h1, o);
    }
    if (lane == 0) { s_h[wid][0] = h0; s_h[wid][1] = h1; }
    __syncthreads();

    if (tid == 0) {
        ull H0 = 0ull, H1 = 0ull;
        #pragma unroll
        for (int w = 0; w < 16; w++) { H0 += s_h[w][0]; H1 += s_h[w][1]; }
        float c[8];
        #pragma unroll
        for (int bn = 0; bn < 4; bn++) {
            c[bn]     = (float)((H0 >> (bn * 16)) & 0xFFFFull);
            c[bn + 4] = (float)((H1 >> (bn * 16)) & 0xFFFFull);
        }
        float ss = 0.0f;
        #pragma unroll
        for (int bn = 0; bn < 8; bn++) ss += c[bn] * c[bn];
        float nrm = fmaxf(sqrtf(ss), 1e-12f);
        float* o1 = out + (a * BSZ + b) * 16 + t * 8;
        float* o2 = out + (b * BSZ + a) * 16 + t * 8;
        #pragma unroll
        for (int bn = 0; bn < 8; bn++) {
            const float val = c[bn] / nrm;
            o1[bn] = val;
            o2[bn] = val;   // hist(a,b) == hist(b,a) by symmetry
        }
    }
}

extern "C" void kernel_launch(void* const* d_in, const int* in_sizes, int n_in,
                              void* d_out, int out_size) {
    const float* m1 = (const float*)d_in[0];
    const float* m2 = (const float*)d_in[1];
    float* out = (float*)d_out;

    split_transpose<<<dim3(BSZ, 8, 8), dim3(32, 8)>>>(m1, m2);

    static int attr_done = 0;
    if (!attr_done) {
        cudaFuncSetAttribute(pair_hmma,
                             cudaFuncAttributeMaxDynamicSharedMemorySize,
                             2 * STAGE_B);
        attr_done = 1;
    }
    pair_hmma<<<dim3(NPAIRS, 2), 512, 2 * STAGE_B>>>(out);
}

// round 5
// speedup vs baseline: 2.4458x; 1.2469x over previous
#include <cuda_runtime.h>
#include <cuda_fp16.h>
#include <cstdint>
#include <math.h>

#define BSZ    64
#define FDIM   256
#define MDIM   128
#define NPAIRS 2080            // 64*65/2 triangular pairs
#define KC     32              // K per chunk
#define NCH    (FDIM / KC)     // 8
#define TILE_B 8192            // 128 rows x 64B (32 fp16)
#define STAGE_B (4 * TILE_B)   // Ah, Al, Bh, Bl = 32KB
#define STAGES 3
typedef unsigned long long ull;

// fp16 split scratch: [tensor][hi/lo][b][m][f], f contiguous = 16 MB
__device__ __align__(16) __half XS[2][2][BSZ][MDIM][FDIM];

// ---------------- pre-pass: transpose + fp16 hi/lo split ----------------
__global__ void split_transpose(const float* __restrict__ m1,
                                const float* __restrict__ m2) {
    __shared__ float tile[32][33];
    const int b  = blockIdx.x;
    const int f0 = blockIdx.y * 32;
    const int mt = blockIdx.z & 3, t = blockIdx.z >> 2;
    const int m0 = mt * 32;
    const float* src = t ? m2 : m1;
    const int tx = threadIdx.x, ty = threadIdx.y;
    #pragma unroll
    for (int i = 0; i < 4; i++) {
        int f = f0 + ty + i * 8;
        tile[ty + i * 8][tx] = src[((size_t)b * FDIM + f) * MDIM + m0 + tx];
    }
    __syncthreads();
    #pragma unroll
    for (int i = 0; i < 4; i++) {
        int m = m0 + ty + i * 8;
        int f = f0 + tx;
        float v = tile[tx][ty + i * 8];
        __half hi = __float2half_rn(v);
        __half lo = __float2half_rn(v - __half2float(hi));
        XS[t][0][b][m][f] = hi;
        XS[t][1][b][m][f] = lo;
    }
}

// ---------------- helpers ----------------
__device__ __forceinline__ uint32_t s2u(const void* p) {
    uint32_t a;
    asm("{ .reg .u64 t; cvta.to.shared.u64 t, %1; cvt.u32.u64 %0, t; }"
        : "=r"(a) : "l"(p));
    return a;
}
__device__ __forceinline__ void cpasync16(uint32_t dst, const void* src) {
    asm volatile("cp.async.cg.shared.global [%0], [%1], 16;"
                 :: "r"(dst), "l"(src));
}
template <int N>
__device__ __forceinline__ void cp_wait() {
    asm volatile("cp.async.wait_group %0;" :: "n"(N) : "memory");
}
__device__ __forceinline__ void ldsm4(uint32_t* r, uint32_t addr) {
    asm volatile("ldmatrix.sync.aligned.m8n8.x4.shared.b16 {%0,%1,%2,%3}, [%4];"
                 : "=r"(r[0]), "=r"(r[1]), "=r"(r[2]), "=r"(r[3]) : "r"(addr));
}
__device__ __forceinline__ void mma16816(float* c, const uint32_t* a,
                                         const uint32_t* b) {
    asm volatile(
        "mma.sync.aligned.m16n8k16.row.col.f32.f16.f16.f32 "
        "{%0,%1,%2,%3}, {%4,%5,%6,%7}, {%8,%9}, {%0,%1,%2,%3};"
        : "+f"(c[0]), "+f"(c[1]), "+f"(c[2]), "+f"(c[3])
        : "r"(a[0]), "r"(a[1]), "r"(a[2]), "r"(a[3]), "r"(b[0]), "r"(b[1]));
}
// swizzled byte offset of (row r, 16B-chunk j) inside a [128][64B] tile
__device__ __forceinline__ uint32_t swz(int r, int j) {
    return (uint32_t)(r * 64 + ((j ^ ((r >> 1) & 3)) << 4));
}

// ---------------- main kernel ----------------
__global__ __launch_bounds__(512, 2)
void pair_hmma(float* __restrict__ out) {
    extern __shared__ char dsm[];
    __shared__ float s_mn[16], s_mx[16];
    __shared__ ull   s_h[16][2];

    const int tid  = threadIdx.x;
    const int lane = tid & 31;
    const int wid  = tid >> 5;          // 0..15
    const int t    = blockIdx.y;

    // decode triangular pair p -> (a, b), a <= b
    int p = blockIdx.x;
    int b = (int)floorf((sqrtf(8.0f * (float)p + 1.0f) - 1.0f) * 0.5f);
    while ((b + 1) * (b + 2) / 2 <= p) ++b;
    while (b * (b + 1) / 2 > p) --b;
    const int a = p - b * (b + 1) / 2;

    const uint32_t sbase = s2u(dsm);
    const int m_base = (wid >> 2) * 32;
    const int n_base = (wid & 3) * 32;

    float acc[2][4][4];
    #pragma unroll
    for (int i = 0; i < 2; i++)
        #pragma unroll
        for (int j = 0; j < 4; j++)
            #pragma unroll
            for (int k = 0; k < 4; k++) acc[i][j][k] = 0.0f;

    // --- per-thread fixed cp.async slot: tile i, row r, chunk j ---
    const int pr = tid >> 2;            // 0..127
    const int pj = tid & 3;             // 0..3
    const uint32_t pdst = swz(pr, pj);  // dst offset within a tile
    const __half* pAh = &XS[t][0][a][pr][pj * 8];
    const __half* pAl = &XS[t][1][a][pr][pj * 8];
    const __half* pBh = &XS[t][0][b][pr][pj * 8];
    const __half* pBl = &XS[t][1][b][pr][pj * 8];

    auto prefetch = [&](int ch) {
        const uint32_t stg = sbase + (uint32_t)(ch % STAGES) * STAGE_B;
        const int off = ch * KC;
        cpasync16(stg + pdst,              pAh + off);
        cpasync16(stg + TILE_B + pdst,     pAl + off);
        cpasync16(stg + 2 * TILE_B + pdst, pBh + off);
        cpasync16(stg + 3 * TILE_B + pdst, pBl + off);
        asm volatile("cp.async.commit_group;" ::: "memory");
    };

    prefetch(0);
    prefetch(1);

    for (int ch = 0; ch < NCH; ch++) {
        if (ch < NCH - 1) cp_wait<1>(); else cp_wait<0>();
        __syncthreads();
        if (ch + 2 < NCH) prefetch(ch + 2);

        const uint32_t aH = sbase + (uint32_t)(ch % STAGES) * STAGE_B;
        const uint32_t aL = aH + TILE_B;
        const uint32_t bH = aH + 2 * TILE_B;
        const uint32_t bL = aH + 3 * TILE_B;

        #pragma unroll
        for (int ks = 0; ks < 2; ks++) {
            uint32_t ah[2][4], al[2][4];
            #pragma unroll
            for (int mt = 0; mt < 2; mt++) {
                const int r = m_base + mt * 16 + (lane & 15);
                const int j = ks * 2 + (lane >> 4);
                const uint32_t off = swz(r, j);
                ldsm4(ah[mt], aH + off);
                ldsm4(al[mt], aL + off);
            }
            #pragma unroll
            for (int t2 = 0; t2 < 2; t2++) {
                uint32_t bh[4], bl[4];
                const int r = n_base + t2 * 16 + ((lane >> 4) << 3) + (lane & 7);
                const int j = ks * 2 + ((lane >> 3) & 1);
                const uint32_t off = swz(r, j);
                ldsm4(bh, bH + off);
                ldsm4(bl, bL + off);
                #pragma unroll
                for (int mt = 0; mt < 2; mt++)
                    #pragma unroll
                    for (int n2 = 0; n2 < 2; n2++) {
                        float* c = acc[mt][t2 * 2 + n2];
                        mma16816(c, ah[mt], &bh[n2 * 2]);
                        mma16816(c, ah[mt], &bl[n2 * 2]);
                        mma16816(c, al[mt], &bh[n2 * 2]);
                    }
            }
        }
    }

    // -------- epilogue: min/max + histogram over all 16384 CTA values --------
    const float* va = &acc[0][0][0];
    float mn = va[0], mx = va[0];
    #pragma unroll
    for (int q = 1; q < 32; q++) { mn = fminf(mn, va[q]); mx = fmaxf(mx, va[q]); }
    #pragma unroll
    for (int o = 16; o > 0; o >>= 1) {
        mn = fminf(mn, __shfl_xor_sync(0xffffffffu, mn, o));
        mx = fmaxf(mx, __shfl_xor_sync(0xffffffffu, mx, o));
    }
    if (lane == 0) { s_mn[wid] = mn; s_mx[wid] = mx; }
    __syncthreads();
    mn = s_mn[0]; mx = s_mx[0];
    #pragma unroll
    for (int w = 1; w < 16; w++) {
        mn = fminf(mn, s_mn[w]); mx = fmaxf(mx, s_mx[w]);
    }
    const float denom = (mx > mn) ? (mx - mn) : 1.0f;

    ull h0 = 0ull, h1 = 0ull;
    #pragma unroll
    for (int q = 0; q < 32; q++) {
        const float tt = (va[q] - mn) / denom * 8.0f;
        int bi = (int)tt;
        if (bi > 7) bi = 7;
        const ull one = 1ull << ((bi & 3) << 4);
        if (bi < 4) h0 += one; else h1 += one;
    }
    #pragma unroll
    for (int o = 16; o > 0; o >>= 1) {
        h0 += __shfl_xor_sync(0xffffffffu, h0, o);
        h1 += __shfl_xor_sync(0xffffffffu, h1, o);
    }
    if (lane == 0) { s_h[wid][0] = h0; s_h[wid][1] = h1; }
    __syncthreads();

    if (tid == 0) {
        ull H0 = 0ull, H1 = 0ull;
        #pragma unroll
        for (int w = 0; w < 16; w++) { H0 += s_h[w][0]; H1 += s_h[w][1]; }
        float c[8];
        #pragma unroll
        for (int bn = 0; bn < 4; bn++) {
            c[bn]     = (float)((H0 >> (bn * 16)) & 0xFFFFull);
            c[bn + 4] = (float)((H1 >> (bn * 16)) & 0xFFFFull);
        }
        float ss = 0.0f;
        #pragma unroll
        for (int bn = 0; bn < 8; bn++) ss += c[bn] * c[bn];
        float nrm = fmaxf(sqrtf(ss), 1e-12f);
        float* o1 = out + (a * BSZ + b) * 16 + t * 8;
        float* o2 = out + (b * BSZ + a) * 16 + t * 8;
        #pragma unroll
        for (int bn = 0; bn < 8; bn++) {
            const float val = c[bn] / nrm;
            o1[bn] = val;
            o2[bn] = val;   // hist(a,b) == hist(b,a) by symmetry
        }
    }
}

extern "C" void kernel_launch(void* const* d_in, const int* in_sizes, int n_in,
                              void* d_out, int out_size) {
    const float* m1 = (const float*)d_in[0];
    const float* m2 = (const float*)d_in[1];
    float* out = (float*)d_out;

    split_transpose<<<dim3(BSZ, 8, 8), dim3(32, 8)>>>(m1, m2);

    cudaFuncSetAttribute(pair_hmma,
                         cudaFuncAttributeMaxDynamicSharedMemorySize,
                         STAGES * STAGE_B);
    pair_hmma<<<dim3(NPAIRS, 2), 512, STAGES * STAGE_B>>>(out);
}

// round 6
// speedup vs baseline: 2.4708x; 1.0102x over previous
#include <cuda_runtime.h>
#include <cuda_fp16.h>
#include <cstdint>
#include <math.h>

#define BSZ    64
#define FDIM   256
#define MDIM   128
#define NPAIRS 2080            // 64*65/2 triangular pairs
#define KC     32              // K per chunk
#define NCH    (FDIM / KC)     // 8
#define TILE_B 8192            // 128 rows x 64B (32 fp16)
#define STAGE_B (4 * TILE_B)   // Ah, Al, Bh, Bl = 32KB
#define STAGES 3
typedef unsigned long long ull;

// fp16 split scratch: [tensor][hi/lo][b][m][f], f contiguous = 16 MB
__device__ __align__(16) __half XS[2][2][BSZ][MDIM][FDIM];

// ---------------- pre-pass: transpose + fp16 hi/lo split ----------------
__global__ void split_transpose(const float* __restrict__ m1,
                                const float* __restrict__ m2) {
    __shared__ float tile[32][33];
    const int b  = blockIdx.x;
    const int f0 = blockIdx.y * 32;
    const int mt = blockIdx.z & 3, t = blockIdx.z >> 2;
    const int m0 = mt * 32;
    const float* src = t ? m2 : m1;
    const int tx = threadIdx.x, ty = threadIdx.y;
    #pragma unroll
    for (int i = 0; i < 4; i++) {
        int f = f0 + ty + i * 8;
        tile[ty + i * 8][tx] = src[((size_t)b * FDIM + f) * MDIM + m0 + tx];
    }
    __syncthreads();
    #pragma unroll
    for (int i = 0; i < 4; i++) {
        int m = m0 + ty + i * 8;
        int f = f0 + tx;
        float v = tile[tx][ty + i * 8];
        __half hi = __float2half_rn(v);
        __half lo = __float2half_rn(v - __half2float(hi));
        XS[t][0][b][m][f] = hi;
        XS[t][1][b][m][f] = lo;
    }
}

// ---------------- helpers ----------------
__device__ __forceinline__ uint32_t s2u(const void* p) {
    uint32_t a;
    asm("{ .reg .u64 t; cvta.to.shared.u64 t, %1; cvt.u32.u64 %0, t; }"
        : "=r"(a) : "l"(p));
    return a;
}
__device__ __forceinline__ void cpasync16(uint32_t dst, const void* src) {
    asm volatile("cp.async.cg.shared.global [%0], [%1], 16;"
                 :: "r"(dst), "l"(src));
}
template <int N>
__device__ __forceinline__ void cp_wait() {
    asm volatile("cp.async.wait_group %0;" :: "n"(N) : "memory");
}
__device__ __forceinline__ void ldsm4(uint32_t* r, uint32_t addr) {
    asm volatile("ldmatrix.sync.aligned.m8n8.x4.shared.b16 {%0,%1,%2,%3}, [%4];"
                 : "=r"(r[0]), "=r"(r[1]), "=r"(r[2]), "=r"(r[3]) : "r"(addr));
}
__device__ __forceinline__ void mma16816(float* c, const uint32_t* a,
                                         const uint32_t* b) {
    asm volatile(
        "mma.sync.aligned.m16n8k16.row.col.f32.f16.f16.f32 "
        "{%0,%1,%2,%3}, {%4,%5,%6,%7}, {%8,%9}, {%0,%1,%2,%3};"
        : "+f"(c[0]), "+f"(c[1]), "+f"(c[2]), "+f"(c[3])
        : "r"(a[0]), "r"(a[1]), "r"(a[2]), "r"(a[3]), "r"(b[0]), "r"(b[1]));
}
// swizzled byte offset of (row r, 16B-chunk j) inside a [128][64B] tile
__device__ __forceinline__ uint32_t swz(int r, int j) {
    return (uint32_t)(r * 64 + ((j ^ ((r >> 1) & 3)) << 4));
}

// ---------------- main kernel ----------------
__global__ __launch_bounds__(512, 2)
void pair_hmma(float* __restrict__ out) {
    extern __shared__ char dsm[];
    __shared__ float s_mn[16], s_mx[16];
    __shared__ ull   s_h[16][2];

    const int tid  = threadIdx.x;
    const int lane = tid & 31;
    const int wid  = tid >> 5;          // 0..15
    const int t    = blockIdx.y;

    // decode triangular pair p -> (a, b), a <= b
    int p = blockIdx.x;
    int b = (int)floorf((sqrtf(8.0f * (float)p + 1.0f) - 1.0f) * 0.5f);
    while ((b + 1) * (b + 2) / 2 <= p) ++b;
    while (b * (b + 1) / 2 > p) --b;
    const int a = p - b * (b + 1) / 2;

    const uint32_t sbase = s2u(dsm);
    const int m_base = (wid >> 2) * 32;
    const int n_base = (wid & 3) * 32;

    // hoisted ldmatrix offsets (chunk-invariant): [mt/t2][ks]
    uint32_t off_a[2][2], off_b[2][2];
    #pragma unroll
    for (int ks = 0; ks < 2; ks++) {
        #pragma unroll
        for (int mt = 0; mt < 2; mt++)
            off_a[mt][ks] = swz(m_base + mt * 16 + (lane & 15),
                                ks * 2 + (lane >> 4));
        #pragma unroll
        for (int t2 = 0; t2 < 2; t2++)
            off_b[t2][ks] = swz(n_base + t2 * 16 + ((lane >> 4) << 3) + (lane & 7),
                                ks * 2 + ((lane >> 3) & 1));
    }

    float acc[2][4][4];
    #pragma unroll
    for (int i = 0; i < 2; i++)
        #pragma unroll
        for (int j = 0; j < 4; j++)
            #pragma unroll
            for (int k = 0; k < 4; k++) acc[i][j][k] = 0.0f;

    // --- per-thread fixed cp.async slot: tile, row r, chunk j ---
    const int pr = tid >> 2;            // 0..127
    const int pj = tid & 3;             // 0..3
    const uint32_t pdst = swz(pr, pj);  // dst offset within a tile
    const __half* pAh = &XS[t][0][a][pr][pj * 8];
    const __half* pAl = &XS[t][1][a][pr][pj * 8];
    const __half* pBh = &XS[t][0][b][pr][pj * 8];
    const __half* pBl = &XS[t][1][b][pr][pj * 8];

    auto prefetch = [&](int ch) {
        const uint32_t stg = sbase + (uint32_t)(ch % STAGES) * STAGE_B;
        const int off = ch * KC;
        cpasync16(stg + pdst,              pAh + off);
        cpasync16(stg + TILE_B + pdst,     pAl + off);
        cpasync16(stg + 2 * TILE_B + pdst, pBh + off);
        cpasync16(stg + 3 * TILE_B + pdst, pBl + off);
        asm volatile("cp.async.commit_group;" ::: "memory");
    };

    prefetch(0);
    prefetch(1);

    #pragma unroll
    for (int ch = 0; ch < NCH; ch++) {
        if (ch < NCH - 1) cp_wait<1>(); else cp_wait<0>();
        __syncthreads();
        if (ch + 2 < NCH) prefetch(ch + 2);

        const uint32_t aH = sbase + (uint32_t)(ch % STAGES) * STAGE_B;
        const uint32_t aL = aH + TILE_B;
        const uint32_t bH = aH + 2 * TILE_B;
        const uint32_t bL = aH + 3 * TILE_B;

        #pragma unroll
        for (int ks = 0; ks < 2; ks++) {
            uint32_t ah[2][4], al[2][4];
            #pragma unroll
            for (int mt = 0; mt < 2; mt++) {
                ldsm4(ah[mt], aH + off_a[mt][ks]);
                ldsm4(al[mt], aL + off_a[mt][ks]);
            }
            #pragma unroll
            for (int t2 = 0; t2 < 2; t2++) {
                uint32_t bh[4], bl[4];
                ldsm4(bh, bH + off_b[t2][ks]);
                ldsm4(bl, bL + off_b[t2][ks]);
                #pragma unroll
                for (int mt = 0; mt < 2; mt++)
                    #pragma unroll
                    for (int n2 = 0; n2 < 2; n2++) {
                        float* c = acc[mt][t2 * 2 + n2];
                        mma16816(c, ah[mt], &bh[n2 * 2]);
                        mma16816(c, ah[mt], &bl[n2 * 2]);
                        mma16816(c, al[mt], &bh[n2 * 2]);
                    }
            }
        }
    }

    // -------- epilogue: min/max + histogram over all 16384 CTA values --------
    const float* va = &acc[0][0][0];
    float mn = va[0], mx = va[0];
    #pragma unroll
    for (int q = 1; q < 32; q++) { mn = fminf(mn, va[q]); mx = fmaxf(mx, va[q]); }
    #pragma unroll
    for (int o = 16; o > 0; o >>= 1) {
        mn = fminf(mn, __shfl_xor_sync(0xffffffffu, mn, o));
        mx = fmaxf(mx, __shfl_xor_sync(0xffffffffu, mx, o));
    }
    if (lane == 0) { s_mn[wid] = mn; s_mx[wid] = mx; }
    __syncthreads();
    mn = s_mn[0]; mx = s_mx[0];
    #pragma unroll
    for (int w = 1; w < 16; w++) {
        mn = fminf(mn, s_mn[w]); mx = fmaxf(mx, s_mx[w]);
    }
    const float denom = (mx > mn) ? (mx - mn) : 1.0f;

    ull h0 = 0ull, h1 = 0ull;
    #pragma unroll
    for (int q = 0; q < 32; q++) {
        const float tt = (va[q] - mn) / denom * 8.0f;
        int bi = (int)tt;
        if (bi > 7) bi = 7;
        const ull one = 1ull << ((bi & 3) << 4);
        if (bi < 4) h0 += one; else h1 += one;
    }
    #pragma unroll
    for (int o = 16; o > 0; o >>= 1) {
        h0 += __shfl_xor_sync(0xffffffffu, h0, o);
        h1 += __shfl_xor_sync(0xffffffffu, h1, o);
    }
    if (lane == 0) { s_h[wid][0] = h0; s_h[wid][1] = h1; }
    __syncthreads();

    if (tid == 0) {
        ull H0 = 0ull, H1 = 0ull;
        #pragma unroll
        for (int w = 0; w < 16; w++) { H0 += s_h[w][0]; H1 += s_h[w][1]; }
        float c[8];
        #pragma unroll
        for (int bn = 0; bn < 4; bn++) {
            c[bn]     = (float)((H0 >> (bn * 16)) & 0xFFFFull);
            c[bn + 4] = (float)((H1 >> (bn * 16)) & 0xFFFFull);
        }
        float ss = 0.0f;
        #pragma unroll
        for (int bn = 0; bn < 8; bn++) ss += c[bn] * c[bn];
        float nrm = fmaxf(sqrtf(ss), 1e-12f);
        float* o1 = out + (a * BSZ + b) * 16 + t * 8;
        float* o2 = out + (b * BSZ + a) * 16 + t * 8;
        #pragma unroll
        for (int bn = 0; bn < 8; bn++) {
            const float val = c[bn] / nrm;
            o1[bn] = val;
            o2[bn] = val;   // hist(a,b) == hist(b,a) by symmetry
        }
    }
}

extern "C" void kernel_launch(void* const* d_in, const int* in_sizes, int n_in,
                              void* d_out, int out_size) {
    const float* m1 = (const float*)d_in[0];
    const float* m2 = (const float*)d_in[1];
    float* out = (float*)d_out;

    split_transpose<<<dim3(BSZ, 8, 8), dim3(32, 8)>>>(m1, m2);

    cudaFuncSetAttribute(pair_hmma,
                         cudaFuncAttributeMaxDynamicSharedMemorySize,
                         STAGES * STAGE_B);
    pair_hmma<<<dim3(NPAIRS, 2), 512, STAGES * STAGE_B>>>(out);
}